// round 14
// baseline (speedup 1.0000x reference)
#include <cuda_runtime.h>
#include <cfloat>

#define BB 4
#define CC 84
#define CP 80          // channels in the max (points[:, :-4])
#define HH 512
#define WW 512
#define HW (HH * WW)
#define HW2 (HW / 2)   // float2 per plane

#define TR 8           // tile rows
#define TC 64          // tile cols (32 float2)
#define PRr (TR + 2)   // 10
#define PC2 34         // padded float2 cols (float cols -2..65)
#define NP (PRr * PC2) // 340 padded float2 positions
#define NT 256         // threads per CTA
#define SCOLS 68       // smem probs cols (float)
#define TILES_X (WW / TC)          // 8
#define TILES_Y (HH / TR)          // 64
#define NTILES (TILES_X * TILES_Y * BB)  // 2048
#define NCTA 296       // 2 persistent CTAs per SM

// per-thread bases for the two padded positions of a tile's prob computation
struct PosBase {
    const float2* b0;
    const float2* b1;
    bool in0, in1;
};

__device__ __forceinline__ PosBase tile_bases(const float2* __restrict__ pts2,
                                              int t, int tid) {
    int bx = t & (TILES_X - 1);
    int by = (t >> 3) & (TILES_Y - 1);
    int b  = t >> 9;
    size_t bbase2 = (size_t)b * CC * HW2;

    int pr0 = tid / PC2, pc0 = tid - pr0 * PC2;
    int gh0 = by * TR + pr0 - 1;
    int gx0 = bx * (TC / 2) + pc0 - 1;
    bool in0 = (gh0 >= 0) & (gh0 < HH) & (gx0 >= 0) & (gx0 < WW / 2);

    int p1 = tid + NT;
    bool act1 = p1 < NP;
    int pr1 = p1 / PC2, pc1 = p1 - pr1 * PC2;
    int gh1 = by * TR + pr1 - 1;
    int gx1 = bx * (TC / 2) + pc1 - 1;
    bool in1 = act1 & (gh1 >= 0) & (gh1 < HH) & (gx1 >= 0) & (gx1 < WW / 2);

    PosBase r;
    r.b0 = pts2 + bbase2 + (size_t)(in0 ? gh0 : 0) * (WW / 2) + (in0 ? gx0 : 0);
    r.b1 = pts2 + bbase2 + (size_t)(in1 ? gh1 : 0) * (WW / 2) + (in1 ? gx1 : 0);
    r.in0 = in0;
    r.in1 = in1;
    return r;
}

// ---------------------------------------------------------------------------
// Persistent, software-pipelined fused NMS:
//   iteration body = [mask(t) from smem] + merged loop over channels
//   { load ch c of tile t+NCTA (max-accumulate)  |  re-read+scale+store ch c of t }
//   + probs->smem(other buffer) + one barrier.
// ---------------------------------------------------------------------------
__global__ void __launch_bounds__(NT, 2)
fused_nms_kernel(const float2* __restrict__ pts2, float2* __restrict__ out2) {
    __shared__ float s_pr[2][PRr * SCOLS];

    const int tid = threadIdx.x;

    // constant per-thread smem positions for prob writes
    const int pr0 = tid / PC2, pc0 = tid - pr0 * PC2;
    const int p1i = tid + NT;
    const bool act1 = p1i < NP;
    const int pr1 = p1i / PC2, pc1 = p1i - pr1 * PC2;

    // interior pixel coords (for mask + apply)
    const int r    = tid >> 5;
    const int lane = tid & 31;

    // ---- Prologue: probs for the first tile ----
    int t = blockIdx.x;
    if (t < NTILES) {
        PosBase pb = tile_bases(pts2, t, tid);
        float2 m0 = make_float2(-FLT_MAX, -FLT_MAX), m1 = m0;
        #pragma unroll 8
        for (int c = 0; c < CP; ++c) {
            float2 v0 = pb.b0[(size_t)c * HW2];
            float2 v1 = pb.b1[(size_t)c * HW2];
            m0.x = fmaxf(m0.x, v0.x);  m0.y = fmaxf(m0.y, v0.y);
            m1.x = fmaxf(m1.x, v1.x);  m1.y = fmaxf(m1.y, v1.y);
        }
        s_pr[0][pr0 * SCOLS + pc0 * 2 + 0] = pb.in0 ? m0.x : 0.0f;
        s_pr[0][pr0 * SCOLS + pc0 * 2 + 1] = pb.in0 ? m0.y : 0.0f;
        if (act1) {
            s_pr[0][pr1 * SCOLS + pc1 * 2 + 0] = pb.in1 ? m1.x : 0.0f;
            s_pr[0][pr1 * SCOLS + pc1 * 2 + 1] = pb.in1 ? m1.y : 0.0f;
        }
    }
    __syncthreads();

    int buf = 0;
    for (; t < NTILES; t += NCTA) {
        // ---- mask for tile t from smem probs ----
        const float* P = s_pr[buf];
        const int cc = lane * 2;
        float2 f;
        #pragma unroll
        for (int j = 0; j < 2; ++j) {
            const int sp = (r + 1) * SCOLS + (cc + j + 2);
            float cen = P[sp];
            bool ok = (cen >  P[sp - SCOLS - 1]) &
                      (cen >  P[sp - SCOLS    ]) &
                      (cen >  P[sp - SCOLS + 1]) &
                      (cen >  P[sp - 1        ]) &
                      (cen >= P[sp + 1        ]) &
                      (cen >= P[sp + SCOLS - 1]) &
                      (cen >= P[sp + SCOLS    ]) &
                      (cen >= P[sp + SCOLS + 1]);
            (j == 0 ? f.x : f.y) = ok ? 1.0f : 0.0f;
        }

        // ---- current tile apply pointers ----
        {
            int bx = t & (TILES_X - 1);
            int by = (t >> 3) & (TILES_Y - 1);
            int b  = t >> 9;
            size_t pix2 = (size_t)b * CC * HW2
                        + (size_t)(by * TR + r) * (WW / 2)
                        + (bx * (TC / 2) + lane);
            const float2* src = pts2 + pix2;
            float2*       dst = out2 + pix2;

            // ---- next tile prob bases (clamped if past the end) ----
            int nt_ = t + NCTA;
            bool hasNext = nt_ < NTILES;
            PosBase nb = tile_bases(pts2, hasNext ? nt_ : t, tid);

            float2 m0 = make_float2(-FLT_MAX, -FLT_MAX), m1 = m0;

            // ---- merged loop: next-tile max loads + current-tile apply ----
            #pragma unroll 4
            for (int c = 0; c < CC; ++c) {
                if (c < CP) {
                    float2 v0 = nb.b0[(size_t)c * HW2];
                    float2 v1 = nb.b1[(size_t)c * HW2];
                    m0.x = fmaxf(m0.x, v0.x);  m0.y = fmaxf(m0.y, v0.y);
                    m1.x = fmaxf(m1.x, v1.x);  m1.y = fmaxf(m1.y, v1.y);
                }
                float2 v = __ldcs(src + (size_t)c * HW2);
                v.x *= f.x;
                v.y *= f.y;
                __stcs(dst + (size_t)c * HW2, v);
            }

            // ---- publish next tile's probs into the other buffer ----
            float* S = s_pr[buf ^ 1];
            S[pr0 * SCOLS + pc0 * 2 + 0] = nb.in0 ? m0.x : 0.0f;
            S[pr0 * SCOLS + pc0 * 2 + 1] = nb.in0 ? m0.y : 0.0f;
            if (act1) {
                S[pr1 * SCOLS + pc1 * 2 + 0] = nb.in1 ? m1.x : 0.0f;
                S[pr1 * SCOLS + pc1 * 2 + 1] = nb.in1 ? m1.y : 0.0f;
            }
        }
        __syncthreads();
        buf ^= 1;
    }
}

// ---------------------------------------------------------------------------
extern "C" void kernel_launch(void* const* d_in, const int* in_sizes, int n_in,
                              void* d_out, int out_size) {
    const float2* pts = (const float2*)d_in[0];
    float2*       out = (float2*)d_out;

    fused_nms_kernel<<<NCTA, NT>>>(pts, out);
}

// round 16
// speedup vs baseline: 1.6451x; 1.6451x over previous
#include <cuda_runtime.h>
#include <cfloat>

#define BB 4
#define CC 84
#define CP 80          // channels participating in the max (points[:, :-4])
#define HH 512
#define WW 512
#define HW (HH * WW)   // 262144
#define HW4 (HW / 4)   // 65536 float4 per plane

// Scratch: channel-max per pixel (4 MB, stays L2-resident into apply).
__device__ float g_probs[BB * HW];

// ---------------------------------------------------------------------------
// Pass 1: probs[b,h,w] = max_{c<80} points[b,c,h,w]  (float4, ascending c).
// Single wave (1024 CTAs) -> at exit, L2 holds the tail channels (~c>=50)
// for ALL pixels. grid (HW4/256, 1, BB), block 256.
// ---------------------------------------------------------------------------
__global__ void __launch_bounds__(256) max_kernel(const float4* __restrict__ pts) {
    int pix = blockIdx.x * 256 + threadIdx.x;      // 0..HW4-1
    int b   = blockIdx.z;
    const float4* base = pts + (size_t)b * CC * HW4 + pix;

    float4 m = base[0];
    #pragma unroll 5
    for (int c = 1; c < CP; ++c) {
        float4 v = base[(size_t)c * HW4];
        m.x = fmaxf(m.x, v.x);
        m.y = fmaxf(m.y, v.y);
        m.z = fmaxf(m.z, v.z);
        m.w = fmaxf(m.w, v.w);
    }
    reinterpret_cast<float4*>(g_probs)[(size_t)b * HW4 + pix] = m;
}

// probs with zero padding outside the image (L2-resident reads)
__device__ __forceinline__ float pr_at(const float* __restrict__ p, int h, int w) {
    if (h < 0 || h >= HH || w < 0 || w >= WW) return 0.0f;
    return __ldg(p + h * WW + w);
}

// ---------------------------------------------------------------------------
// Pass 2 (fused mask + apply): one thread owns one float4 pixel-group and all
// 84 channels, sweeping channels DESCENDING so the first ~30 channel planes
// hit the L2 residue left by max_kernel. __ldcs/__stcs keep the cold traffic
// from evicting the not-yet-consumed hot planes.
// grid (HW4/256, 1, BB), block 256 -> single wave.
// ---------------------------------------------------------------------------
__global__ void __launch_bounds__(256) apply_kernel(const float4* __restrict__ pts,
                                                    float4* __restrict__ out) {
    int pix = blockIdx.x * 256 + threadIdx.x;      // 0..HW4-1
    int b   = blockIdx.z;
    int p4  = pix << 2;                            // first pixel of the group
    int h   = p4 >> 9;
    int w0  = p4 & (WW - 1);                       // w0..w0+3 in one row

    // ---- inline 3x3 NMS mask for the 4 pixels ----
    const float* probs = g_probs + (size_t)b * HW;
    float up[6], mid[6], dn[6];
    #pragma unroll
    for (int j = 0; j < 6; ++j) {
        int w = w0 - 1 + j;
        up[j]  = pr_at(probs, h - 1, w);
        mid[j] = pr_at(probs, h,     w);
        dn[j]  = pr_at(probs, h + 1, w);
    }
    float fm[4];
    #pragma unroll
    for (int j = 0; j < 4; ++j) {
        float cen = mid[j + 1];
        // before center: strict > ; after center: >=
        bool ok = (cen >  up[j]) & (cen >  up[j + 1]) & (cen >  up[j + 2]) &
                  (cen >  mid[j]) &
                  (cen >= mid[j + 2]) &
                  (cen >= dn[j]) & (cen >= dn[j + 1]) & (cen >= dn[j + 2]);
        fm[j] = ok ? 1.0f : 0.0f;
    }

    // ---- apply: channels descending (83 -> 0) to consume L2 residue ----
    const float4* src = pts + (size_t)b * CC * HW4 + pix;
    float4*       dst = out + (size_t)b * CC * HW4 + pix;
    #pragma unroll 4
    for (int c = CC - 1; c >= 0; --c) {
        float4 v = __ldcs(src + (size_t)c * HW4);  // hit-or-evict-first
        v.x *= fm[0];
        v.y *= fm[1];
        v.z *= fm[2];
        v.w *= fm[3];
        __stcs(dst + (size_t)c * HW4, v);          // streaming store
    }
}

// ---------------------------------------------------------------------------
extern "C" void kernel_launch(void* const* d_in, const int* in_sizes, int n_in,
                              void* d_out, int out_size) {
    const float4* pts = (const float4*)d_in[0];
    float4*       out = (float4*)d_out;

    dim3 blk(256);
    dim3 grid(HW4 / 256, 1, BB);                   // 1024 CTAs, single wave

    max_kernel  <<<grid, blk>>>(pts);
    apply_kernel<<<grid, blk>>>(pts, out);
}